// round 5
// baseline (speedup 1.0000x reference)
#include <cuda_runtime.h>
#include <cuda_bf16.h>
#include <cstdint>

// FrozenBNBEmbedding: fused blockwise-dequant + embedding gather.
// BLOCK (4096) == DIM (4096) => block id of any element of row r is r:
//   out[row, d] = code[ weight[token, d] ] * absmax[token]
//
// R4: persistent-CTA version. Grid = 148*8 = one full wave; each CTA strides
// over ~7 rows, prefetching the next row's token+absmax (a 2-deep dependent
// load chain) while streaming the current row. Eliminates wave-transition
// and per-CTA index-chain ramp costs seen as the gap between 68.8% DRAM busy
// and the 7.1 TB/s app-level rate. Streaming stores (.cs) kept from R3.
//
// Inputs (metadata order):
//   d_in[0] = input  : int32 [4, 2048]      token ids (8192 rows)
//   d_in[1] = weight : int32 [50400, 4096]  int8 codes stored as int32
//   d_in[2] = absmax : fp32  [50400]        per-block scale (block == row)
//   d_in[3] = code   : fp32  [256]          dequant LUT
// Output: fp32 [4, 2048, 4096]

#define DIM 4096
#define VEC (DIM / 4)  // 1024 int4/float4 per row
#define NTHREADS 256
#define GRID_CTAS (148 * 8)

__device__ __forceinline__ void stg_cs_v4(float4* p, float4 v) {
    asm volatile("st.global.cs.v4.f32 [%0], {%1, %2, %3, %4};"
                 :: "l"(p), "f"(v.x), "f"(v.y), "f"(v.z), "f"(v.w)
                 : "memory");
}

__global__ __launch_bounds__(NTHREADS, 8)
void bnb_embed_kernel(const int* __restrict__ tokens,
                      const int* __restrict__ weight,
                      const float* __restrict__ absmax,
                      const float* __restrict__ code,
                      float* __restrict__ out,
                      int n_rows)
{
    __shared__ float s_code[256];
    const int t = threadIdx.x;
    if (t < 256) s_code[t] = code[t];
    __syncthreads();

    const int stride = gridDim.x;
    int row = blockIdx.x;
    if (row >= n_rows) return;

    // Prologue: resolve the first row's index chain.
    int token = __ldg(&tokens[row]);
    float amax = __ldg(&absmax[token]);

    while (row < n_rows) {
        // Prefetch next row's token/scale chain while this row streams.
        const int next_row = row + stride;
        int next_token = 0;
        if (next_row < n_rows) next_token = __ldg(&tokens[next_row]);

        const int4* __restrict__ src = reinterpret_cast<const int4*>(weight) +
                                       (size_t)token * VEC;
        float4* __restrict__ dst = reinterpret_cast<float4*>(out) +
                                   (size_t)row * VEC;

        float next_amax = 0.0f;
        if (next_row < n_rows) next_amax = __ldg(&absmax[next_token]);

        #pragma unroll
        for (int k = 0; k < VEC / NTHREADS; k++) {
            const int i = t + k * NTHREADS;
            int4 q = src[i];
            float4 v;
            v.x = s_code[q.x & 0xFF] * amax;
            v.y = s_code[q.y & 0xFF] * amax;
            v.z = s_code[q.z & 0xFF] * amax;
            v.w = s_code[q.w & 0xFF] * amax;
            stg_cs_v4(dst + i, v);
        }

        row = next_row;
        token = next_token;
        amax = next_amax;
    }
}

extern "C" void kernel_launch(void* const* d_in, const int* in_sizes, int n_in,
                              void* d_out, int out_size)
{
    const int*   tokens = (const int*)d_in[0];
    const int*   weight = (const int*)d_in[1];
    const float* absmax = (const float*)d_in[2];
    const float* code   = (const float*)d_in[3];
    float*       out    = (float*)d_out;

    int n_rows = in_sizes[0];  // 8192
    int grid = GRID_CTAS < n_rows ? GRID_CTAS : n_rows;
    bnb_embed_kernel<<<grid, NTHREADS>>>(tokens, weight, absmax, code, out, n_rows);
}

// round 6
// speedup vs baseline: 1.1140x; 1.1140x over previous
#include <cuda_runtime.h>
#include <cuda_bf16.h>
#include <cstdint>

// FrozenBNBEmbedding: fused blockwise-dequant + embedding gather.
// BLOCK (4096) == DIM (4096) => block id of any element of row r is r:
//   out[row, d] = code[ weight[token, d] ] * absmax[token]
//
// R5: R3 shape (grid=8192, 1 row/CTA, 256 thr — proven best in 3 head-to-heads)
// with two fixes to the store path:
//   - st.global.cs asm no longer carries a "memory" clobber, so the compiler
//     can hoist loads above stores (R3's clobber serialized LDG/STG 1:1).
//   - all 4 int4 row-loads explicitly front-batched into registers before any
//     store: per-thread MLP_p1 = 4 outstanding LDG.128.
//
// Inputs (metadata order):
//   d_in[0] = input  : int32 [4, 2048]      token ids (8192 rows)
//   d_in[1] = weight : int32 [50400, 4096]  int8 codes stored as int32
//   d_in[2] = absmax : fp32  [50400]        per-block scale (block == row)
//   d_in[3] = code   : fp32  [256]          dequant LUT
// Output: fp32 [4, 2048, 4096]

#define DIM 4096
#define VEC (DIM / 4)            // 1024 int4/float4 per row
#define NTHREADS 256
#define ITER (VEC / NTHREADS)    // 4

__device__ __forceinline__ void stg_cs_v4(float4* p, float4 v) {
    // No "memory" clobber: output buffer is only read by the host after the
    // kernel; we don't need this store ordered against anything the compiler
    // tracks. volatile keeps it from being eliminated.
    asm volatile("st.global.cs.v4.f32 [%0], {%1, %2, %3, %4};"
                 :: "l"(p), "f"(v.x), "f"(v.y), "f"(v.z), "f"(v.w));
}

__global__ __launch_bounds__(NTHREADS, 8)
void bnb_embed_kernel(const int* __restrict__ tokens,
                      const int* __restrict__ weight,
                      const float* __restrict__ absmax,
                      const float* __restrict__ code,
                      float* __restrict__ out)
{
    __shared__ float s_code[256];
    const int t = threadIdx.x;
    if (t < 256) s_code[t] = code[t];
    __syncthreads();

    const int row = blockIdx.x;
    const int token = __ldg(&tokens[row]);
    const float amax = __ldg(&absmax[token]);

    const int4* __restrict__ src = reinterpret_cast<const int4*>(weight) +
                                   (size_t)token * VEC;
    float4* __restrict__ dst = reinterpret_cast<float4*>(out) +
                               (size_t)row * VEC;

    // Front-batch all 4 LDG.128 before any dependent work / stores.
    int4 q[ITER];
    #pragma unroll
    for (int k = 0; k < ITER; k++)
        q[k] = src[t + k * NTHREADS];

    #pragma unroll
    for (int k = 0; k < ITER; k++) {
        float4 v;
        v.x = s_code[q[k].x & 0xFF] * amax;
        v.y = s_code[q[k].y & 0xFF] * amax;
        v.z = s_code[q[k].z & 0xFF] * amax;
        v.w = s_code[q[k].w & 0xFF] * amax;
        stg_cs_v4(dst + t + k * NTHREADS, v);
    }
}

extern "C" void kernel_launch(void* const* d_in, const int* in_sizes, int n_in,
                              void* d_out, int out_size)
{
    const int*   tokens = (const int*)d_in[0];
    const int*   weight = (const int*)d_in[1];
    const float* absmax = (const float*)d_in[2];
    const float* code   = (const float*)d_in[3];
    float*       out    = (float*)d_out;

    int n_rows = in_sizes[0];  // 8192
    bnb_embed_kernel<<<n_rows, NTHREADS>>>(tokens, weight, absmax, code, out);
}